// round 7
// baseline (speedup 1.0000x reference)
#include <cuda_runtime.h>
#include <cuda_bf16.h>
#include <cstdint>

// Problem constants
#define Gg 8
#define Nn 1024
#define Ff 128
#define Hh 256
#define Ll 4
#define Bb 64
#define CAP 128

// ---------------- scratch (device globals) ----------------------------------
__device__ __align__(16) float g_X0[Gg * Nn * Hh];
__device__ __align__(16) float g_X [Gg * Nn * Hh];
__device__ __align__(16) float g_Y [Gg * Nn * Hh];            // fp32 Y (last layer)
__device__ __align__(16) uint32_t g_Yb[Gg * Nn * Hh / 2];     // bf16x2 Y (relu layers)
__device__ __align__(16) float g_Wt   [Ll * Hh * Hh];         // Ws^T (tf32-rounded)
__device__ __align__(16) float g_WtIn [Hh * Ff];              // W_in^T (tf32-rounded)
__device__ unsigned short g_cols[(long)Gg * Nn * CAP];
__device__ __align__(16) float g_vals[(long)Gg * Nn * CAP];
__device__ int   g_nnz[Gg * Nn];
__device__ float g_maskf[Bb * Nn];
__device__ float g_cnt[Bb];
__device__ int   g_mask_mode;

// ---------------- helpers ----------------------------------------------------
__device__ __forceinline__ float f2tf32(float x) {
    uint32_t r;
    asm("cvt.rna.tf32.f32 %0, %1;" : "=r"(r) : "f"(x));
    return __uint_as_float(r);
}
__device__ __forceinline__ uint32_t frag_tf32(float x) {
    uint32_t r;
    asm("cvt.rna.tf32.f32 %0, %1;" : "=r"(r) : "f"(x));
    return r;
}

__device__ __forceinline__ void mma_tf32(float& c0, float& c1, float& c2, float& c3,
                                         uint32_t a0, uint32_t a1, uint32_t a2, uint32_t a3,
                                         uint32_t b0, uint32_t b1) {
    asm volatile(
        "mma.sync.aligned.m16n8k8.row.col.f32.tf32.tf32.f32 "
        "{%0,%1,%2,%3}, {%4,%5,%6,%7}, {%8,%9}, {%0,%1,%2,%3};"
        : "+f"(c0), "+f"(c1), "+f"(c2), "+f"(c3)
        : "r"(a0), "r"(a1), "r"(a2), "r"(a3), "r"(b0), "r"(b1));
}

__device__ __forceinline__ void cp16(void* dst_smem, const void* src) {
    uint32_t d = (uint32_t)__cvta_generic_to_shared(dst_smem);
    asm volatile("cp.async.cg.shared.global [%0], [%1], 16;"
                 :: "r"(d), "l"(src) : "memory");
}
#define CP_COMMIT() asm volatile("cp.async.commit_group;" ::: "memory")
#define CP_WAIT2()  asm volatile("cp.async.wait_group 2;" ::: "memory")
#define CP_WAIT1()  asm volatile("cp.async.wait_group 1;" ::: "memory")
#define CP_WAIT0()  asm volatile("cp.async.wait_group 0;" ::: "memory")

// ---------------- detect mask dtype + zero d_out -----------------------------
__global__ void detect_zero_kernel(const unsigned int* __restrict__ m,
                                   float* __restrict__ out) {
    out[(long)blockIdx.x * 256 + threadIdx.x] = 0.0f;
    if (blockIdx.x != 0) return;
    __shared__ int sh_f, sh_b;
    if (threadIdx.x == 0) { sh_f = 0; sh_b = 0; }
    __syncthreads();
    int f = 0, b = 0;
    for (int i = threadIdx.x; i < 16384; i += blockDim.x) {
        unsigned int w = m[i];
        if (w == 0x3F800000u) f = 1;
        if (w > 1u && (w & ~0x01010101u) == 0u) b = 1;
    }
    if (f) atomicOr(&sh_f, 1);
    if (b) atomicOr(&sh_b, 1);
    __syncthreads();
    if (threadIdx.x == 0) g_mask_mode = sh_f ? 1 : (sh_b ? 2 : 0);
}

// ---------------- CSR build + mask expand (merged) ---------------------------
__global__ void csr_mask_kernel(const float* __restrict__ Adj,
                                const void* __restrict__ mraw) {
    __shared__ int cnt;
    if (blockIdx.y < Gg) {
        int g = blockIdx.y;
        int n = blockIdx.x;
        long rbase = (long)g * Nn + n;
        const float* row = Adj + rbase * Nn;
        if (threadIdx.x == 0) cnt = 0;
        __syncthreads();
        for (int m = threadIdx.x; m < Nn; m += blockDim.x) {
            float v = row[m];
            if (v != 0.0f) {
                int p = atomicAdd(&cnt, 1);
                if (p < CAP) {
                    g_cols[rbase * CAP + p] = (unsigned short)m;
                    g_vals[rbase * CAP + p] = v;
                }
            }
        }
        __syncthreads();
        if (threadIdx.x == 0) g_nnz[rbase] = cnt < CAP ? cnt : CAP;
    } else {
        int b = blockIdx.x;
        if (b >= Bb) return;
        int mode = g_mask_mode;
        if (threadIdx.x == 0) cnt = 0;
        __syncthreads();
        int local = 0;
        for (int n = threadIdx.x; n < Nn; n += blockDim.x) {
            long idx = (long)b * Nn + n;
            bool on;
            if (mode == 1)      on = ((const float*)mraw)[idx] != 0.0f;
            else if (mode == 2) on = ((const unsigned char*)mraw)[idx] != 0;
            else                on = ((const int*)mraw)[idx] != 0;
            g_maskf[idx] = on ? 1.0f : 0.0f;
            local += on ? 1 : 0;
        }
        atomicAdd(&cnt, local);
        __syncthreads();
        if (threadIdx.x == 0) g_cnt[b] = (float)(cnt < 1 ? 1 : cnt);
    }
}

// ---------------- merged weight transpose (rounds B to tf32) -----------------
__global__ void transpose_all_kernel(const float* __restrict__ Ws,
                                     const float* __restrict__ W_in) {
    __shared__ float tile[32][33];
    int z = blockIdx.z;
    const float* src;
    float* dst;
    int K;
    if (z < Ll) { src = Ws + (long)z * Hh * Hh; dst = g_Wt + (long)z * Hh * Hh; K = Hh; }
    else {
        if (blockIdx.x >= Ff / 32) return;
        src = W_in; dst = g_WtIn; K = Ff;
    }
    int k0 = blockIdx.x * 32, h0 = blockIdx.y * 32;
    int x = threadIdx.x, y = threadIdx.y;   // 32 x 8
    #pragma unroll
    for (int j = 0; j < 32; j += 8)
        tile[y + j][x] = src[(long)(k0 + y + j) * Hh + h0 + x];
    __syncthreads();
    #pragma unroll
    for (int j = 0; j < 32; j += 8)
        dst[(long)(h0 + y + j) * K + k0 + x] = f2tf32(tile[x][y + j]);
}

// ---------------- tf32 mma.sync GEMM, 3-stage cp.async, 64x64 tile -----------
// act(A[g] @ Bt^T + bias). CTA 256 thr (8 warps, 4x2), warp tile 16x32, BK=32.
// A fragments rounded to tf32 in-register; Bt is pre-rounded.
#define APITCH 36
#define ABUF (64 * APITCH)
#define BBUF (64 * APITCH)
#define NSTAGE 3
#define GEMM_SMEM ((NSTAGE * (ABUF + BBUF)) * sizeof(float))

template<int KDIM, bool RELU, bool BIAS, bool OUTBF16>
__global__ __launch_bounds__(256)
void mma_gemm_kernel(const float* __restrict__ A,
                     const float* __restrict__ Bt,
                     float* __restrict__ C,
                     const float* __restrict__ bias) {
    constexpr int NC = KDIM / 32;
    extern __shared__ float sh[];
    float* AsBase = sh;                       // [NSTAGE][64][36]
    float* BsBase = sh + NSTAGE * ABUF;       // [NSTAGE][64][36]

    const int t = threadIdx.x;
    const int wid = t >> 5, lane = t & 31;
    const int gid = lane >> 2, tig = lane & 3;
    const int wy = wid >> 1, wx = wid & 1;    // 4x2 warp grid, warp tile 16x32
    const int col0 = blockIdx.x * 64;
    const int row0 = blockIdx.y * 64;
    const int g = blockIdx.z;

    const float* Ag = A + ((long)g * Nn + row0) * KDIM;
    float* Cg = OUTBF16 ? nullptr : (C + ((long)g * Nn + row0) * Hh);
    uint32_t* Yb = OUTBF16 ? (g_Yb + ((long)g * Nn + row0) * (Hh / 2)) : nullptr;

    // A: 64x32 = 512 x16B / 256 thr = 2 each; B same.
    #define ISSUE(c, buf) do { \
        _Pragma("unroll") \
        for (int i = 0; i < 2; i++) { \
            int f = t + i * 256; \
            int row = f >> 3, c4 = f & 7; \
            cp16(&AsBase[(buf) * ABUF + row * APITCH + c4 * 4], \
                 &Ag[(long)row * KDIM + (c) * 32 + c4 * 4]); \
        } \
        _Pragma("unroll") \
        for (int i = 0; i < 2; i++) { \
            int f = t + i * 256; \
            int n = f >> 3, c4 = f & 7; \
            cp16(&BsBase[(buf) * BBUF + n * APITCH + c4 * 4], \
                 &Bt[(long)(col0 + n) * KDIM + (c) * 32 + c4 * 4]); \
        } \
        CP_COMMIT(); \
    } while (0)

    float acc[4][4] = {};   // [nt][4]

    ISSUE(0, 0);
    ISSUE(1, 1);
    if (NC > 2) ISSUE(2, 2);

    int buf = 0;
    for (int c = 0; c < NC; c++) {
        int rem = NC - 1 - c;
        if (rem >= 2) CP_WAIT2(); else if (rem == 1) CP_WAIT1(); else CP_WAIT0();
        __syncthreads();

        const float* As = AsBase + buf * ABUF;
        const float* Bs = BsBase + buf * BBUF;

        #pragma unroll
        for (int ks = 0; ks < 4; ks++) {
            const int kk = ks * 8 + tig;
            const int mr = wy * 16 + gid;
            uint32_t a0 = frag_tf32(As[(mr    ) * APITCH + kk]);
            uint32_t a1 = frag_tf32(As[(mr + 8) * APITCH + kk]);
            uint32_t a2 = frag_tf32(As[(mr    ) * APITCH + kk + 4]);
            uint32_t a3 = frag_tf32(As[(mr + 8) * APITCH + kk + 4]);
            uint32_t b[4][2];
            #pragma unroll
            for (int nt = 0; nt < 4; nt++) {
                int nr = wx * 32 + nt * 8 + gid;
                b[nt][0] = __float_as_uint(Bs[nr * APITCH + kk]);
                b[nt][1] = __float_as_uint(Bs[nr * APITCH + kk + 4]);
            }
            #pragma unroll
            for (int nt = 0; nt < 4; nt++)
                mma_tf32(acc[nt][0], acc[nt][1], acc[nt][2], acc[nt][3],
                         a0, a1, a2, a3, b[nt][0], b[nt][1]);
        }
        __syncthreads();
        if (c + NSTAGE < NC) ISSUE(c + NSTAGE, buf);
        buf = (buf + 1 == NSTAGE) ? 0 : buf + 1;
    }

    // epilogue
    {
        int r = wy * 16 + gid;
        #pragma unroll
        for (int nt = 0; nt < 4; nt++) {
            int cc = col0 + wx * 32 + nt * 8 + 2 * tig;
            float b0 = 0.f, b1 = 0.f;
            if (BIAS) { b0 = bias[cc]; b1 = bias[cc + 1]; }
            float v0 = acc[nt][0] + b0;
            float v1 = acc[nt][1] + b1;
            float v2 = acc[nt][2] + b0;
            float v3 = acc[nt][3] + b1;
            if (RELU) {
                v0 = fmaxf(v0, 0.f); v1 = fmaxf(v1, 0.f);
                v2 = fmaxf(v2, 0.f); v3 = fmaxf(v3, 0.f);
            }
            if (OUTBF16) {
                __nv_bfloat162 p0 = __float22bfloat162_rn(make_float2(v0, v1));
                __nv_bfloat162 p1 = __float22bfloat162_rn(make_float2(v2, v3));
                Yb[(long)r * (Hh / 2) + cc / 2]       = *reinterpret_cast<uint32_t*>(&p0);
                Yb[(long)(r + 8) * (Hh / 2) + cc / 2] = *reinterpret_cast<uint32_t*>(&p1);
            } else {
                *reinterpret_cast<float2*>(&Cg[(long)r * Hh + cc]) =
                    make_float2(v0, v1);
                *reinterpret_cast<float2*>(&Cg[(long)(r + 8) * Hh + cc]) =
                    make_float2(v2, v3);
            }
        }
    }
}

// ---------------- SpMM: X = act(A_sparse @ Y + bias) ------------------------
template<bool LAST>
__global__ __launch_bounds__(128)
void spmm_kernel(const float* __restrict__ bias) {
    int g = blockIdx.y;
    int n = blockIdx.x;
    int t = threadIdx.x;
    int lane = t & 31, wid = t >> 5;
    long rbase = (long)g * Nn + n;
    int nnz = g_nnz[rbase];

    __shared__ unsigned short scol[CAP];
    __shared__ float sval[CAP];
    for (int j = t; j < nnz; j += 128) {
        scol[j] = g_cols[rbase * CAP + j];
        sval[j] = g_vals[rbase * CAP + j];
    }
    __syncthreads();

    float a0 = 0.f, a1 = 0.f;
    if (!LAST) {
        const uint32_t* Yg = g_Yb + (long)g * Nn * (Hh / 2);
        int j = 0;
        for (; j + 8 <= nnz; j += 8) {
            uint32_t w[8];
            #pragma unroll
            for (int q = 0; q < 8; q++)
                w[q] = Yg[(long)scol[j + q] * (Hh / 2) + t];
            #pragma unroll
            for (int q = 0; q < 8; q++) {
                float2 f = __bfloat1622float2(
                    *reinterpret_cast<__nv_bfloat162*>(&w[q]));
                a0 += sval[j + q] * f.x;
                a1 += sval[j + q] * f.y;
            }
        }
        if (j + 4 <= nnz) {
            uint32_t w[4];
            #pragma unroll
            for (int q = 0; q < 4; q++)
                w[q] = Yg[(long)scol[j + q] * (Hh / 2) + t];
            #pragma unroll
            for (int q = 0; q < 4; q++) {
                float2 f = __bfloat1622float2(
                    *reinterpret_cast<__nv_bfloat162*>(&w[q]));
                a0 += sval[j + q] * f.x;
                a1 += sval[j + q] * f.y;
            }
            j += 4;
        }
        for (; j < nnz; j++) {
            uint32_t w = Yg[(long)scol[j] * (Hh / 2) + t];
            float2 f = __bfloat1622float2(
                *reinterpret_cast<__nv_bfloat162*>(&w));
            a0 += sval[j] * f.x;
            a1 += sval[j] * f.y;
        }
    } else {
        const float2* Yg = reinterpret_cast<const float2*>(g_Y + (long)g * Nn * Hh);
        int j = 0;
        for (; j + 8 <= nnz; j += 8) {
            float2 w[8];
            #pragma unroll
            for (int q = 0; q < 8; q++)
                w[q] = Yg[(long)scol[j + q] * (Hh / 2) + t];
            #pragma unroll
            for (int q = 0; q < 8; q++) {
                a0 += sval[j + q] * w[q].x;
                a1 += sval[j + q] * w[q].y;
            }
        }
        if (j + 4 <= nnz) {
            float2 w[4];
            #pragma unroll
            for (int q = 0; q < 4; q++)
                w[q] = Yg[(long)scol[j + q] * (Hh / 2) + t];
            #pragma unroll
            for (int q = 0; q < 4; q++) {
                a0 += sval[j + q] * w[q].x;
                a1 += sval[j + q] * w[q].y;
            }
            j += 4;
        }
        for (; j < nnz; j++) {
            float2 w = Yg[(long)scol[j] * (Hh / 2) + t];
            a0 += sval[j] * w.x;
            a1 += sval[j] * w.y;
        }
    }

    float2 bv = *reinterpret_cast<const float2*>(&bias[2 * t]);
    float v0 = a0 + bv.x, v1 = a1 + bv.y;

    float2* Xp = reinterpret_cast<float2*>(g_X) + rbase * (Hh / 2) + t;
    if (!LAST) {
        *Xp = make_float2(fmaxf(v0, 0.f), fmaxf(v1, 0.f));
    } else {
        __shared__ float smax[4], ssum[4];
        float m = fmaxf(v0, v1);
        #pragma unroll
        for (int off = 16; off > 0; off >>= 1)
            m = fmaxf(m, __shfl_xor_sync(0xFFFFFFFFu, m, off));
        if (lane == 0) smax[wid] = m;
        __syncthreads();
        m = fmaxf(fmaxf(smax[0], smax[1]), fmaxf(smax[2], smax[3]));
        float e0 = expf(v0 - m), e1 = expf(v1 - m);
        float s = e0 + e1;
        #pragma unroll
        for (int off = 16; off > 0; off >>= 1)
            s += __shfl_xor_sync(0xFFFFFFFFu, s, off);
        if (lane == 0) ssum[wid] = s;
        __syncthreads();
        s = (ssum[0] + ssum[1]) + (ssum[2] + ssum[3]);
        float inv = 1.0f / s;
        float2 x0 = reinterpret_cast<const float2*>(g_X0)[rbase * (Hh / 2) + t];
        *Xp = make_float2(e0 * inv + x0.x, e1 * inv + x0.y);
    }
}

// ---------------- per-sample masked mean -------------------------------------
__global__ void masked_mean_kernel(const int* __restrict__ graph,
                                   float* __restrict__ out) {
    int b = blockIdx.x;
    int chunk = blockIdx.y;
    int h = threadIdx.x;
    int g = graph[b];
    const float* xg = g_X + ((long)g * Nn + chunk * 128) * Hh;
    const float* mb = g_maskf + (long)b * Nn + chunk * 128;
    float acc = 0.f;
    #pragma unroll 4
    for (int n = 0; n < 128; n++) {
        float mv = mb[n];
        if (mv != 0.f) acc += xg[(long)n * Hh + h];
    }
    atomicAdd(&out[(long)b * Hh + h], acc / g_cnt[b]);
}

// ---------------- launch -----------------------------------------------------
extern "C" void kernel_launch(void* const* d_in, const int* in_sizes, int n_in,
                              void* d_out, int out_size) {
    const int*   graph = (const int*)  d_in[0];
    const void*  mask  =               d_in[1];
    const float* xs    = (const float*)d_in[2];
    const float* Adj   = (const float*)d_in[3];
    const float* W_in  = (const float*)d_in[4];
    const float* b_in  = (const float*)d_in[5];
    const float* Ws    = (const float*)d_in[6];
    const float* bs    = (const float*)d_in[7];
    float* out = (float*)d_out;

    float *pX0, *pX, *pY, *pWt, *pWtIn;
    cudaGetSymbolAddress((void**)&pX0,   g_X0);
    cudaGetSymbolAddress((void**)&pX,    g_X);
    cudaGetSymbolAddress((void**)&pY,    g_Y);
    cudaGetSymbolAddress((void**)&pWt,   g_Wt);
    cudaGetSymbolAddress((void**)&pWtIn, g_WtIn);

    cudaFuncSetAttribute(mma_gemm_kernel<Ff, true, true, false>,
        cudaFuncAttributeMaxDynamicSharedMemorySize, (int)GEMM_SMEM);
    cudaFuncSetAttribute(mma_gemm_kernel<Hh, false, false, true>,
        cudaFuncAttributeMaxDynamicSharedMemorySize, (int)GEMM_SMEM);
    cudaFuncSetAttribute(mma_gemm_kernel<Hh, false, false, false>,
        cudaFuncAttributeMaxDynamicSharedMemorySize, (int)GEMM_SMEM);

    // zero d_out + detect mask dtype
    detect_zero_kernel<<<Bb, 256>>>((const unsigned int*)mask, out);

    // CSR build + mask expand
    dim3 cm_grid(Nn, Gg + 1);
    csr_mask_kernel<<<cm_grid, 256>>>(Adj, mask);

    // weight transposes (tf32-rounded)
    transpose_all_kernel<<<dim3(8, 8, Ll + 1), dim3(32, 8)>>>(Ws, W_in);

    dim3 ggrid(Hh / 64, Nn / 64, Gg);   // 4 x 16 x 8 = 512 CTAs

    // X0 = relu(xs @ W_in + b_in)
    mma_gemm_kernel<Ff, true, true, false>
        <<<ggrid, 256, GEMM_SMEM>>>(xs, pWtIn, pX0, b_in);

    dim3 sp_grid(Nn, Gg);
    const float* xin = pX0;
    for (int i = 0; i < Ll; i++) {
        if (i < Ll - 1) {
            mma_gemm_kernel<Hh, false, false, true>
                <<<ggrid, 256, GEMM_SMEM>>>(xin, pWt + (long)i * Hh * Hh,
                                            nullptr, nullptr);
            spmm_kernel<false><<<sp_grid, 128>>>(bs + (long)i * Hh);
        } else {
            mma_gemm_kernel<Hh, false, false, false>
                <<<ggrid, 256, GEMM_SMEM>>>(xin, pWt + (long)i * Hh * Hh,
                                            pY, nullptr);
            spmm_kernel<true><<<sp_grid, 128>>>(bs + (long)i * Hh);
        }
        xin = pX;
    }

    dim3 mm_grid(Bb, Nn / 128);
    masked_mean_kernel<<<mm_grid, Hh>>>(graph, out);
}

// round 8
// speedup vs baseline: 1.0901x; 1.0901x over previous
#include <cuda_runtime.h>
#include <cuda_bf16.h>
#include <cstdint>

// Problem constants
#define Gg 8
#define Nn 1024
#define Ff 128
#define Hh 256
#define Ll 4
#define Bb 64
#define CAP 128

// ---------------- scratch (device globals) ----------------------------------
__device__ __align__(16) float g_X0[Gg * Nn * Hh];
__device__ __align__(16) float g_X [Gg * Nn * Hh];
__device__ __align__(16) uint32_t g_Yb[Gg * Nn * Hh / 2];     // bf16x2 Y (all layers)
__device__ __align__(16) float g_Wt   [Ll * Hh * Hh];         // Ws^T (tf32-rounded)
__device__ __align__(16) float g_WtIn [Hh * Ff];              // W_in^T (tf32-rounded)
__device__ unsigned short g_cols[(long)Gg * Nn * CAP];
__device__ __align__(16) float g_vals[(long)Gg * Nn * CAP];
__device__ int   g_nnz[Gg * Nn];
__device__ float g_maskf[Bb * Nn];
__device__ float g_cnt[Bb];
__device__ int   g_mask_mode;

// ---------------- helpers ----------------------------------------------------
__device__ __forceinline__ float f2tf32(float x) {
    uint32_t r;
    asm("cvt.rna.tf32.f32 %0, %1;" : "=r"(r) : "f"(x));
    return __uint_as_float(r);
}
__device__ __forceinline__ uint32_t frag_tf32(float x) {
    uint32_t r;
    asm("cvt.rna.tf32.f32 %0, %1;" : "=r"(r) : "f"(x));
    return r;
}

__device__ __forceinline__ void mma_tf32(float& c0, float& c1, float& c2, float& c3,
                                         uint32_t a0, uint32_t a1, uint32_t a2, uint32_t a3,
                                         uint32_t b0, uint32_t b1) {
    asm volatile(
        "mma.sync.aligned.m16n8k8.row.col.f32.tf32.tf32.f32 "
        "{%0,%1,%2,%3}, {%4,%5,%6,%7}, {%8,%9}, {%0,%1,%2,%3};"
        : "+f"(c0), "+f"(c1), "+f"(c2), "+f"(c3)
        : "r"(a0), "r"(a1), "r"(a2), "r"(a3), "r"(b0), "r"(b1));
}

__device__ __forceinline__ void cp16(void* dst_smem, const void* src) {
    uint32_t d = (uint32_t)__cvta_generic_to_shared(dst_smem);
    asm volatile("cp.async.cg.shared.global [%0], [%1], 16;"
                 :: "r"(d), "l"(src) : "memory");
}
#define CP_COMMIT() asm volatile("cp.async.commit_group;" ::: "memory")
#define CP_WAIT1()  asm volatile("cp.async.wait_group 1;" ::: "memory")
#define CP_WAIT0()  asm volatile("cp.async.wait_group 0;" ::: "memory")

// ---------------- prep: zero d_out + detect mask dtype + weight transposes ---
// grid 384 blocks of (32,8):
//   blocks [0,64):   zero d_out row; block 0 also classifies mask dtype
//   blocks [64,384): weight transposes (z = idx/64: 0..3 Ws layers, 4 = W_in)
__global__ void prep_kernel(const unsigned int* __restrict__ m,
                            float* __restrict__ out,
                            const float* __restrict__ Ws,
                            const float* __restrict__ W_in) {
    const int t = threadIdx.y * 32 + threadIdx.x;
    const int bid = blockIdx.x;

    if (bid < Bb) {
        out[(long)bid * 256 + t] = 0.0f;
        if (bid != 0) return;
        __shared__ int sh_f, sh_b;
        if (t == 0) { sh_f = 0; sh_b = 0; }
        __syncthreads();
        int f = 0, b = 0;
        for (int i = t; i < 16384; i += 256) {
            unsigned int w = m[i];
            if (w == 0x3F800000u) f = 1;
            if (w > 1u && (w & ~0x01010101u) == 0u) b = 1;
        }
        if (f) atomicOr(&sh_f, 1);
        if (b) atomicOr(&sh_b, 1);
        __syncthreads();
        if (t == 0) g_mask_mode = sh_f ? 1 : (sh_b ? 2 : 0);
        return;
    }

    // transpose section
    __shared__ float tile[32][33];
    int idx = bid - Bb;
    int z = idx >> 6;           // 0..4
    int rem = idx & 63;
    int bx = rem & 7, by = rem >> 3;
    const float* src;
    float* dst;
    int K;
    if (z < Ll) { src = Ws + (long)z * Hh * Hh; dst = g_Wt + (long)z * Hh * Hh; K = Hh; }
    else {
        if (bx >= Ff / 32) return;
        src = W_in; dst = g_WtIn; K = Ff;
    }
    int k0 = bx * 32, h0 = by * 32;
    int x = threadIdx.x, y = threadIdx.y;
    #pragma unroll
    for (int j = 0; j < 32; j += 8)
        tile[y + j][x] = src[(long)(k0 + y + j) * Hh + h0 + x];
    __syncthreads();
    #pragma unroll
    for (int j = 0; j < 32; j += 8)
        dst[(long)(h0 + y + j) * K + k0 + x] = f2tf32(tile[x][y + j]);
}

// ---------------- CSR build + mask expand (merged) ---------------------------
__global__ void csr_mask_kernel(const float* __restrict__ Adj,
                                const void* __restrict__ mraw) {
    __shared__ int cnt;
    if (blockIdx.y < Gg) {
        int g = blockIdx.y;
        int n = blockIdx.x;
        long rbase = (long)g * Nn + n;
        const float* row = Adj + rbase * Nn;
        if (threadIdx.x == 0) cnt = 0;
        __syncthreads();
        for (int m = threadIdx.x; m < Nn; m += blockDim.x) {
            float v = row[m];
            if (v != 0.0f) {
                int p = atomicAdd(&cnt, 1);
                if (p < CAP) {
                    g_cols[rbase * CAP + p] = (unsigned short)m;
                    g_vals[rbase * CAP + p] = v;
                }
            }
        }
        __syncthreads();
        if (threadIdx.x == 0) g_nnz[rbase] = cnt < CAP ? cnt : CAP;
    } else {
        int b = blockIdx.x;
        if (b >= Bb) return;
        int mode = g_mask_mode;
        if (threadIdx.x == 0) cnt = 0;
        __syncthreads();
        int local = 0;
        for (int n = threadIdx.x; n < Nn; n += blockDim.x) {
            long idx = (long)b * Nn + n;
            bool on;
            if (mode == 1)      on = ((const float*)mraw)[idx] != 0.0f;
            else if (mode == 2) on = ((const unsigned char*)mraw)[idx] != 0;
            else                on = ((const int*)mraw)[idx] != 0;
            g_maskf[idx] = on ? 1.0f : 0.0f;
            local += on ? 1 : 0;
        }
        atomicAdd(&cnt, local);
        __syncthreads();
        if (threadIdx.x == 0) g_cnt[b] = (float)(cnt < 1 ? 1 : cnt);
    }
}

// ---------------- tf32 mma.sync GEMM, 3-stage single-sync ring, 128x64 tile --
// act(A[g] @ Bt^T + bias). CTA 256 thr (8 warps, 4x2), warp tile 32x32, BK=32.
// A fragments rounded to tf32 in-register; Bt is pre-rounded.
#define APITCH 36
#define ABUF (128 * APITCH)
#define BBUF (64 * APITCH)
#define NSTAGE 3
#define GEMM_SMEM ((NSTAGE * (ABUF + BBUF)) * sizeof(float))

template<int KDIM, bool RELU, bool BIAS, bool OUTBF16>
__global__ __launch_bounds__(256)
void mma_gemm_kernel(const float* __restrict__ A,
                     const float* __restrict__ Bt,
                     float* __restrict__ C,
                     const float* __restrict__ bias) {
    constexpr int NC = KDIM / 32;
    extern __shared__ float sh[];
    float* AsBase = sh;                       // [NSTAGE][128][36]
    float* BsBase = sh + NSTAGE * ABUF;       // [NSTAGE][64][36]

    const int t = threadIdx.x;
    const int wid = t >> 5, lane = t & 31;
    const int gid = lane >> 2, tig = lane & 3;
    const int wy = wid >> 1, wx = wid & 1;    // 4x2 warp grid, warp tile 32x32
    const int col0 = blockIdx.x * 64;
    const int row0 = blockIdx.y * 128;
    const int g = blockIdx.z;

    const float* Ag = A + ((long)g * Nn + row0) * KDIM;
    float* Cg = OUTBF16 ? nullptr : (C + ((long)g * Nn + row0) * Hh);
    uint32_t* Yb = OUTBF16 ? (g_Yb + ((long)g * Nn + row0) * (Hh / 2)) : nullptr;

    // A: 128x32 = 1024 x16B / 256 thr = 4 each; B: 64x32 = 512 / 256 = 2 each.
    #define ISSUE(c, s) do { \
        _Pragma("unroll") \
        for (int i = 0; i < 4; i++) { \
            int f = t + i * 256; \
            int row = f >> 3, c4 = f & 7; \
            cp16(&AsBase[(s) * ABUF + row * APITCH + c4 * 4], \
                 &Ag[(long)row * KDIM + (c) * 32 + c4 * 4]); \
        } \
        _Pragma("unroll") \
        for (int i = 0; i < 2; i++) { \
            int f = t + i * 256; \
            int n = f >> 3, c4 = f & 7; \
            cp16(&BsBase[(s) * BBUF + n * APITCH + c4 * 4], \
                 &Bt[(long)(col0 + n) * KDIM + (c) * 32 + c4 * 4]); \
        } \
        CP_COMMIT(); \
    } while (0)

    float acc[2][4][4] = {};

    ISSUE(0, 0);
    ISSUE(1, 1);

    for (int c = 0; c < NC; c++) {
        if (c + 1 < NC) CP_WAIT1(); else CP_WAIT0();
        __syncthreads();
        // refill the stage consumed at iter c-1 (protected by the barrier above)
        if (c + 2 < NC) ISSUE(c + 2, (c + 2) % NSTAGE);

        const float* As = AsBase + (c % NSTAGE) * ABUF;
        const float* Bs = BsBase + (c % NSTAGE) * BBUF;

        #pragma unroll
        for (int ks = 0; ks < 4; ks++) {
            const int kk = ks * 8 + tig;
            uint32_t a[2][4];
            #pragma unroll
            for (int mt = 0; mt < 2; mt++) {
                int mr = wy * 32 + mt * 16 + gid;
                a[mt][0] = frag_tf32(As[(mr    ) * APITCH + kk]);
                a[mt][1] = frag_tf32(As[(mr + 8) * APITCH + kk]);
                a[mt][2] = frag_tf32(As[(mr    ) * APITCH + kk + 4]);
                a[mt][3] = frag_tf32(As[(mr + 8) * APITCH + kk + 4]);
            }
            uint32_t b[4][2];
            #pragma unroll
            for (int nt = 0; nt < 4; nt++) {
                int nr = wx * 32 + nt * 8 + gid;
                b[nt][0] = __float_as_uint(Bs[nr * APITCH + kk]);
                b[nt][1] = __float_as_uint(Bs[nr * APITCH + kk + 4]);
            }
            #pragma unroll
            for (int mt = 0; mt < 2; mt++)
                #pragma unroll
                for (int nt = 0; nt < 4; nt++)
                    mma_tf32(acc[mt][nt][0], acc[mt][nt][1],
                             acc[mt][nt][2], acc[mt][nt][3],
                             a[mt][0], a[mt][1], a[mt][2], a[mt][3],
                             b[nt][0], b[nt][1]);
        }
    }

    // epilogue
    #pragma unroll
    for (int mt = 0; mt < 2; mt++) {
        int r = wy * 32 + mt * 16 + gid;
        #pragma unroll
        for (int nt = 0; nt < 4; nt++) {
            int cc = col0 + wx * 32 + nt * 8 + 2 * tig;
            float b0 = 0.f, b1 = 0.f;
            if (BIAS) { b0 = bias[cc]; b1 = bias[cc + 1]; }
            float v0 = acc[mt][nt][0] + b0;
            float v1 = acc[mt][nt][1] + b1;
            float v2 = acc[mt][nt][2] + b0;
            float v3 = acc[mt][nt][3] + b1;
            if (RELU) {
                v0 = fmaxf(v0, 0.f); v1 = fmaxf(v1, 0.f);
                v2 = fmaxf(v2, 0.f); v3 = fmaxf(v3, 0.f);
            }
            if (OUTBF16) {
                __nv_bfloat162 p0 = __float22bfloat162_rn(make_float2(v0, v1));
                __nv_bfloat162 p1 = __float22bfloat162_rn(make_float2(v2, v3));
                Yb[(long)r * (Hh / 2) + cc / 2]       = *reinterpret_cast<uint32_t*>(&p0);
                Yb[(long)(r + 8) * (Hh / 2) + cc / 2] = *reinterpret_cast<uint32_t*>(&p1);
            } else {
                *reinterpret_cast<float2*>(&Cg[(long)r * Hh + cc]) =
                    make_float2(v0, v1);
                *reinterpret_cast<float2*>(&Cg[(long)(r + 8) * Hh + cc]) =
                    make_float2(v2, v3);
            }
        }
    }
}

// ---------------- SpMM: X = act(A_sparse @ Y + bias), Y in bf16x2 ------------
template<bool LAST>
__global__ __launch_bounds__(128)
void spmm_kernel(const float* __restrict__ bias) {
    int g = blockIdx.y;
    int n = blockIdx.x;
    int t = threadIdx.x;
    int lane = t & 31, wid = t >> 5;
    long rbase = (long)g * Nn + n;
    int nnz = g_nnz[rbase];

    __shared__ unsigned short scol[CAP];
    __shared__ float sval[CAP];
    for (int j = t; j < nnz; j += 128) {
        scol[j] = g_cols[rbase * CAP + j];
        sval[j] = g_vals[rbase * CAP + j];
    }
    __syncthreads();

    const uint32_t* Yg = g_Yb + (long)g * Nn * (Hh / 2);
    float a0 = 0.f, a1 = 0.f;
    int j = 0;
    for (; j + 8 <= nnz; j += 8) {
        uint32_t w[8];
        #pragma unroll
        for (int q = 0; q < 8; q++)
            w[q] = Yg[(long)scol[j + q] * (Hh / 2) + t];
        #pragma unroll
        for (int q = 0; q < 8; q++) {
            float2 f = __bfloat1622float2(*reinterpret_cast<__nv_bfloat162*>(&w[q]));
            a0 += sval[j + q] * f.x;
            a1 += sval[j + q] * f.y;
        }
    }
    if (j + 4 <= nnz) {
        uint32_t w[4];
        #pragma unroll
        for (int q = 0; q < 4; q++)
            w[q] = Yg[(long)scol[j + q] * (Hh / 2) + t];
        #pragma unroll
        for (int q = 0; q < 4; q++) {
            float2 f = __bfloat1622float2(*reinterpret_cast<__nv_bfloat162*>(&w[q]));
            a0 += sval[j + q] * f.x;
            a1 += sval[j + q] * f.y;
        }
        j += 4;
    }
    for (; j < nnz; j++) {
        uint32_t w = Yg[(long)scol[j] * (Hh / 2) + t];
        float2 f = __bfloat1622float2(*reinterpret_cast<__nv_bfloat162*>(&w));
        a0 += sval[j] * f.x;
        a1 += sval[j] * f.y;
    }

    float2 bv = *reinterpret_cast<const float2*>(&bias[2 * t]);
    float v0 = a0 + bv.x, v1 = a1 + bv.y;

    float2* Xp = reinterpret_cast<float2*>(g_X) + rbase * (Hh / 2) + t;
    if (!LAST) {
        *Xp = make_float2(fmaxf(v0, 0.f), fmaxf(v1, 0.f));
    } else {
        __shared__ float smax[4], ssum[4];
        float m = fmaxf(v0, v1);
        #pragma unroll
        for (int off = 16; off > 0; off >>= 1)
            m = fmaxf(m, __shfl_xor_sync(0xFFFFFFFFu, m, off));
        if (lane == 0) smax[wid] = m;
        __syncthreads();
        m = fmaxf(fmaxf(smax[0], smax[1]), fmaxf(smax[2], smax[3]));
        float e0 = expf(v0 - m), e1 = expf(v1 - m);
        float s = e0 + e1;
        #pragma unroll
        for (int off = 16; off > 0; off >>= 1)
            s += __shfl_xor_sync(0xFFFFFFFFu, s, off);
        if (lane == 0) ssum[wid] = s;
        __syncthreads();
        s = (ssum[0] + ssum[1]) + (ssum[2] + ssum[3]);
        float inv = 1.0f / s;
        float2 x0 = reinterpret_cast<const float2*>(g_X0)[rbase * (Hh / 2) + t];
        *Xp = make_float2(e0 * inv + x0.x, e1 * inv + x0.y);
    }
}

// ---------------- per-sample masked mean -------------------------------------
__global__ void masked_mean_kernel(const int* __restrict__ graph,
                                   float* __restrict__ out) {
    int b = blockIdx.x;
    int chunk = blockIdx.y;
    int h = threadIdx.x;
    int g = graph[b];
    const float* xg = g_X + ((long)g * Nn + chunk * 128) * Hh;
    const float* mb = g_maskf + (long)b * Nn + chunk * 128;
    float acc = 0.f;
    #pragma unroll 4
    for (int n = 0; n < 128; n++) {
        float mv = mb[n];
        if (mv != 0.f) acc += xg[(long)n * Hh + h];
    }
    atomicAdd(&out[(long)b * Hh + h], acc / g_cnt[b]);
}

// ---------------- launch -----------------------------------------------------
extern "C" void kernel_launch(void* const* d_in, const int* in_sizes, int n_in,
                              void* d_out, int out_size) {
    const int*   graph = (const int*)  d_in[0];
    const void*  mask  =               d_in[1];
    const float* xs    = (const float*)d_in[2];
    const float* Adj   = (const float*)d_in[3];
    const float* W_in  = (const float*)d_in[4];
    const float* b_in  = (const float*)d_in[5];
    const float* Ws    = (const float*)d_in[6];
    const float* bs    = (const float*)d_in[7];
    float* out = (float*)d_out;

    float *pX0, *pX, *pWt, *pWtIn;
    cudaGetSymbolAddress((void**)&pX0,   g_X0);
    cudaGetSymbolAddress((void**)&pX,    g_X);
    cudaGetSymbolAddress((void**)&pWt,   g_Wt);
    cudaGetSymbolAddress((void**)&pWtIn, g_WtIn);

    cudaFuncSetAttribute(mma_gemm_kernel<Ff, true, true, false>,
        cudaFuncAttributeMaxDynamicSharedMemorySize, (int)GEMM_SMEM);
    cudaFuncSetAttribute(mma_gemm_kernel<Hh, false, false, true>,
        cudaFuncAttributeMaxDynamicSharedMemorySize, (int)GEMM_SMEM);

    // prep: zero d_out + detect mask dtype + weight transposes (one launch)
    prep_kernel<<<Bb + 320, dim3(32, 8)>>>((const unsigned int*)mask, out, Ws, W_in);

    // CSR build + mask expand
    dim3 cm_grid(Nn, Gg + 1);
    csr_mask_kernel<<<cm_grid, 256>>>(Adj, mask);

    dim3 ggrid(Hh / 64, Nn / 128, Gg);   // 256 CTAs

    // X0 = relu(xs @ W_in + b_in)  [fp32 out]
    mma_gemm_kernel<Ff, true, true, false>
        <<<ggrid, 256, GEMM_SMEM>>>(xs, pWtIn, pX0, b_in);

    dim3 sp_grid(Nn, Gg);
    const float* xin = pX0;
    for (int i = 0; i < Ll; i++) {
        mma_gemm_kernel<Hh, false, false, true>
            <<<ggrid, 256, GEMM_SMEM>>>(xin, pWt + (long)i * Hh * Hh,
                                        nullptr, nullptr);
        if (i < Ll - 1)
            spmm_kernel<false><<<sp_grid, 128>>>(bs + (long)i * Hh);
        else
            spmm_kernel<true><<<sp_grid, 128>>>(bs + (long)i * Hh);
        xin = pX;
    }

    dim3 mm_grid(Bb, Nn / 128);
    masked_mean_kernel<<<mm_grid, Hh>>>(graph, out);
}

// round 9
// speedup vs baseline: 1.2300x; 1.1283x over previous
#include <cuda_runtime.h>
#include <cuda_bf16.h>
#include <cstdint>

// Problem constants
#define Gg 8
#define Nn 1024
#define Ff 128
#define Hh 256
#define Ll 4
#define Bb 64
#define CAP 128

// ---------------- scratch (device globals) ----------------------------------
__device__ __align__(16) float    g_X0 [Gg * Nn * Hh];          // fp32 residual
__device__ __align__(16) uint32_t g_X0b[Gg * Nn * Hh / 2];      // bf16x2 copy of X0
__device__ __align__(16) float    g_X  [Gg * Nn * Hh];          // fp32 final x
__device__ __align__(16) uint32_t g_Xb [Gg * Nn * Hh / 2];      // bf16x2 inter-layer x
__device__ __align__(16) uint32_t g_Yb [Gg * Nn * Hh / 2];      // bf16x2 Y = x @ W
__device__ __align__(16) uint32_t g_Wtb[Ll * Hh * Hh / 2];      // bf16x2 Ws^T [l][n][k]
__device__ __align__(16) float    g_WtIn[Hh * Ff];              // W_in^T (tf32-rounded)
__device__ unsigned short g_cols[(long)Gg * Nn * CAP];
__device__ __align__(16) float g_vals[(long)Gg * Nn * CAP];
__device__ int   g_nnz[Gg * Nn];
__device__ float g_maskf[Bb * Nn];
__device__ float g_cnt[Bb];
__device__ int   g_mask_mode;

// ---------------- helpers ----------------------------------------------------
__device__ __forceinline__ float f2tf32(float x) {
    uint32_t r;
    asm("cvt.rna.tf32.f32 %0, %1;" : "=r"(r) : "f"(x));
    return __uint_as_float(r);
}
__device__ __forceinline__ uint32_t frag_tf32(float x) {
    uint32_t r;
    asm("cvt.rna.tf32.f32 %0, %1;" : "=r"(r) : "f"(x));
    return r;
}

__device__ __forceinline__ void mma_tf32(float& c0, float& c1, float& c2, float& c3,
                                         uint32_t a0, uint32_t a1, uint32_t a2, uint32_t a3,
                                         uint32_t b0, uint32_t b1) {
    asm volatile(
        "mma.sync.aligned.m16n8k8.row.col.f32.tf32.tf32.f32 "
        "{%0,%1,%2,%3}, {%4,%5,%6,%7}, {%8,%9}, {%0,%1,%2,%3};"
        : "+f"(c0), "+f"(c1), "+f"(c2), "+f"(c3)
        : "r"(a0), "r"(a1), "r"(a2), "r"(a3), "r"(b0), "r"(b1));
}
__device__ __forceinline__ void mma_bf16(float& c0, float& c1, float& c2, float& c3,
                                         uint32_t a0, uint32_t a1, uint32_t a2, uint32_t a3,
                                         uint32_t b0, uint32_t b1) {
    asm volatile(
        "mma.sync.aligned.m16n8k16.row.col.f32.bf16.bf16.f32 "
        "{%0,%1,%2,%3}, {%4,%5,%6,%7}, {%8,%9}, {%0,%1,%2,%3};"
        : "+f"(c0), "+f"(c1), "+f"(c2), "+f"(c3)
        : "r"(a0), "r"(a1), "r"(a2), "r"(a3), "r"(b0), "r"(b1));
}

__device__ __forceinline__ void cp16(void* dst_smem, const void* src) {
    uint32_t d = (uint32_t)__cvta_generic_to_shared(dst_smem);
    asm volatile("cp.async.cg.shared.global [%0], [%1], 16;"
                 :: "r"(d), "l"(src) : "memory");
}
#define CP_COMMIT() asm volatile("cp.async.commit_group;" ::: "memory")
#define CP_WAIT1()  asm volatile("cp.async.wait_group 1;" ::: "memory")
#define CP_WAIT0()  asm volatile("cp.async.wait_group 0;" ::: "memory")

// ---------------- prep: zero d_out + detect mask + weight transposes ---------
// grid 384 blocks of (32,8):
//   [0,64): zero d_out row; block 0 classifies mask dtype
//   [64,384): transposes (z = idx/64: 0..3 Ws->bf16, 4 = W_in->tf32 fp32)
__global__ void prep_kernel(const unsigned int* __restrict__ m,
                            float* __restrict__ out,
                            const float* __restrict__ Ws,
                            const float* __restrict__ W_in) {
    const int t = threadIdx.y * 32 + threadIdx.x;
    const int bid = blockIdx.x;

    if (bid < Bb) {
        out[(long)bid * 256 + t] = 0.0f;
        if (bid != 0) return;
        __shared__ int sh_f, sh_b;
        if (t == 0) { sh_f = 0; sh_b = 0; }
        __syncthreads();
        int f = 0, b = 0;
        for (int i = t; i < 16384; i += 256) {
            unsigned int w = m[i];
            if (w == 0x3F800000u) f = 1;
            if (w > 1u && (w & ~0x01010101u) == 0u) b = 1;
        }
        if (f) atomicOr(&sh_f, 1);
        if (b) atomicOr(&sh_b, 1);
        __syncthreads();
        if (t == 0) g_mask_mode = sh_f ? 1 : (sh_b ? 2 : 0);
        return;
    }

    __shared__ float tile[32][33];
    int idx = bid - Bb;
    int z = idx >> 6;           // 0..4
    int rem = idx & 63;
    int bx = rem & 7, by = rem >> 3;
    int x = threadIdx.x, y = threadIdx.y;

    if (z < Ll) {
        const float* src = Ws + (long)z * Hh * Hh;
        __nv_bfloat16* dst = reinterpret_cast<__nv_bfloat16*>(g_Wtb) + (long)z * Hh * Hh;
        int k0 = bx * 32, h0 = by * 32;
        #pragma unroll
        for (int j = 0; j < 32; j += 8)
            tile[y + j][x] = src[(long)(k0 + y + j) * Hh + h0 + x];
        __syncthreads();
        #pragma unroll
        for (int j = 0; j < 32; j += 8)
            dst[(long)(h0 + y + j) * Hh + k0 + x] = __float2bfloat16(tile[x][y + j]);
    } else {
        if (bx >= Ff / 32) return;
        int k0 = bx * 32, h0 = by * 32;
        #pragma unroll
        for (int j = 0; j < 32; j += 8)
            tile[y + j][x] = W_in[(long)(k0 + y + j) * Hh + h0 + x];
        __syncthreads();
        #pragma unroll
        for (int j = 0; j < 32; j += 8)
            g_WtIn[(long)(h0 + y + j) * Ff + k0 + x] = f2tf32(tile[x][y + j]);
    }
}

// ---------------- CSR build + mask expand (merged) ---------------------------
__global__ void csr_mask_kernel(const float* __restrict__ Adj,
                                const void* __restrict__ mraw) {
    __shared__ int cnt;
    if (blockIdx.y < Gg) {
        int g = blockIdx.y;
        int n = blockIdx.x;
        long rbase = (long)g * Nn + n;
        const float* row = Adj + rbase * Nn;
        if (threadIdx.x == 0) cnt = 0;
        __syncthreads();
        for (int m = threadIdx.x; m < Nn; m += blockDim.x) {
            float v = row[m];
            if (v != 0.0f) {
                int p = atomicAdd(&cnt, 1);
                if (p < CAP) {
                    g_cols[rbase * CAP + p] = (unsigned short)m;
                    g_vals[rbase * CAP + p] = v;
                }
            }
        }
        __syncthreads();
        if (threadIdx.x == 0) g_nnz[rbase] = cnt < CAP ? cnt : CAP;
    } else {
        int b = blockIdx.x;
        if (b >= Bb) return;
        int mode = g_mask_mode;
        if (threadIdx.x == 0) cnt = 0;
        __syncthreads();
        int local = 0;
        for (int n = threadIdx.x; n < Nn; n += blockDim.x) {
            long idx = (long)b * Nn + n;
            bool on;
            if (mode == 1)      on = ((const float*)mraw)[idx] != 0.0f;
            else if (mode == 2) on = ((const unsigned char*)mraw)[idx] != 0;
            else                on = ((const int*)mraw)[idx] != 0;
            g_maskf[idx] = on ? 1.0f : 0.0f;
            local += on ? 1 : 0;
        }
        atomicAdd(&cnt, local);
        __syncthreads();
        if (threadIdx.x == 0) g_cnt[b] = (float)(cnt < 1 ? 1 : cnt);
    }
}

// ---------------- tf32 input GEMM (fp32 A), 3-stage single-sync, 128x64 ------
// X0 = relu(xs @ W_in^T + b_in), writes fp32 X0 AND bf16 copy X0b.
#define APITCH 36
#define ABUF (128 * APITCH)
#define BBUF (64 * APITCH)
#define NSTAGE 3
#define GEMM32_SMEM ((NSTAGE * (ABUF + BBUF)) * sizeof(float))

__global__ __launch_bounds__(256)
void mma_gemm_in_kernel(const float* __restrict__ A,
                        const float* __restrict__ Bt,
                        const float* __restrict__ bias) {
    constexpr int KDIM = Ff, NC = KDIM / 32;
    extern __shared__ float sh[];
    float* AsBase = sh;
    float* BsBase = sh + NSTAGE * ABUF;

    const int t = threadIdx.x;
    const int wid = t >> 5, lane = t & 31;
    const int gid = lane >> 2, tig = lane & 3;
    const int wy = wid >> 1, wx = wid & 1;
    const int col0 = blockIdx.x * 64;
    const int row0 = blockIdx.y * 128;
    const int g = blockIdx.z;

    const float* Ag = A + ((long)g * Nn + row0) * KDIM;
    float* Cg = g_X0 + ((long)g * Nn + row0) * Hh;
    uint32_t* Cb = g_X0b + ((long)g * Nn + row0) * (Hh / 2);

    #define ISSUE32(c, s) do { \
        _Pragma("unroll") \
        for (int i = 0; i < 4; i++) { \
            int f = t + i * 256; \
            int row = f >> 3, c4 = f & 7; \
            cp16(&AsBase[(s) * ABUF + row * APITCH + c4 * 4], \
                 &Ag[(long)row * KDIM + (c) * 32 + c4 * 4]); \
        } \
        _Pragma("unroll") \
        for (int i = 0; i < 2; i++) { \
            int f = t + i * 256; \
            int n = f >> 3, c4 = f & 7; \
            cp16(&BsBase[(s) * BBUF + n * APITCH + c4 * 4], \
                 &Bt[(long)(col0 + n) * KDIM + (c) * 32 + c4 * 4]); \
        } \
        CP_COMMIT(); \
    } while (0)

    float acc[2][4][4] = {};
    ISSUE32(0, 0);
    ISSUE32(1, 1);

    for (int c = 0; c < NC; c++) {
        if (c + 1 < NC) CP_WAIT1(); else CP_WAIT0();
        __syncthreads();
        if (c + 2 < NC) ISSUE32(c + 2, (c + 2) % NSTAGE);

        const float* As = AsBase + (c % NSTAGE) * ABUF;
        const float* Bs = BsBase + (c % NSTAGE) * BBUF;

        #pragma unroll
        for (int ks = 0; ks < 4; ks++) {
            const int kk = ks * 8 + tig;
            uint32_t a[2][4];
            #pragma unroll
            for (int mt = 0; mt < 2; mt++) {
                int mr = wy * 32 + mt * 16 + gid;
                a[mt][0] = frag_tf32(As[(mr    ) * APITCH + kk]);
                a[mt][1] = frag_tf32(As[(mr + 8) * APITCH + kk]);
                a[mt][2] = frag_tf32(As[(mr    ) * APITCH + kk + 4]);
                a[mt][3] = frag_tf32(As[(mr + 8) * APITCH + kk + 4]);
            }
            uint32_t b[4][2];
            #pragma unroll
            for (int nt = 0; nt < 4; nt++) {
                int nr = wx * 32 + nt * 8 + gid;
                b[nt][0] = __float_as_uint(Bs[nr * APITCH + kk]);
                b[nt][1] = __float_as_uint(Bs[nr * APITCH + kk + 4]);
            }
            #pragma unroll
            for (int mt = 0; mt < 2; mt++)
                #pragma unroll
                for (int nt = 0; nt < 4; nt++)
                    mma_tf32(acc[mt][nt][0], acc[mt][nt][1],
                             acc[mt][nt][2], acc[mt][nt][3],
                             a[mt][0], a[mt][1], a[mt][2], a[mt][3],
                             b[nt][0], b[nt][1]);
        }
    }

    #pragma unroll
    for (int mt = 0; mt < 2; mt++) {
        int r = wy * 32 + mt * 16 + gid;
        #pragma unroll
        for (int nt = 0; nt < 4; nt++) {
            int cc = col0 + wx * 32 + nt * 8 + 2 * tig;
            float b0 = bias[cc], b1 = bias[cc + 1];
            float v0 = fmaxf(acc[mt][nt][0] + b0, 0.f);
            float v1 = fmaxf(acc[mt][nt][1] + b1, 0.f);
            float v2 = fmaxf(acc[mt][nt][2] + b0, 0.f);
            float v3 = fmaxf(acc[mt][nt][3] + b1, 0.f);
            *reinterpret_cast<float2*>(&Cg[(long)r * Hh + cc]) = make_float2(v0, v1);
            *reinterpret_cast<float2*>(&Cg[(long)(r + 8) * Hh + cc]) = make_float2(v2, v3);
            __nv_bfloat162 p0 = __float22bfloat162_rn(make_float2(v0, v1));
            __nv_bfloat162 p1 = __float22bfloat162_rn(make_float2(v2, v3));
            Cb[(long)r * (Hh / 2) + cc / 2]       = *reinterpret_cast<uint32_t*>(&p0);
            Cb[(long)(r + 8) * (Hh / 2) + cc / 2] = *reinterpret_cast<uint32_t*>(&p1);
        }
    }
}

// ---------------- bf16 layer GEMM: Yb = Xb @ Wtb^T ----------------------------
// A bf16 [g][1024][256], B bf16 [256][256] K-major. CTA 128x64, BK=32 (bf16).
// smem rows: 16 data words (uint32=bf16x2) + 4 pad = 20-word pitch (conflict-free).
#define WPITCH 20
#define ABUFW (128 * WPITCH)
#define BBUFW (64 * WPITCH)
#define GEMM16_SMEM ((NSTAGE * (ABUFW + BBUFW)) * sizeof(uint32_t))

__global__ __launch_bounds__(256)
void mma_gemm_bf16_kernel(const uint32_t* __restrict__ A,   // bf16x2 words
                          const uint32_t* __restrict__ Bt,  // bf16x2 words
                          uint32_t* __restrict__ Yout) {
    constexpr int NC = Hh / 32;      // 8 chunks of 32 bf16
    constexpr int KW = Hh / 2;       // 128 words per row
    extern __shared__ uint32_t shw[];
    uint32_t* AsBase = shw;
    uint32_t* BsBase = shw + NSTAGE * ABUFW;

    const int t = threadIdx.x;
    const int wid = t >> 5, lane = t & 31;
    const int gid = lane >> 2, tig = lane & 3;
    const int wy = wid >> 1, wx = wid & 1;
    const int col0 = blockIdx.x * 64;
    const int row0 = blockIdx.y * 128;
    const int g = blockIdx.z;

    const uint32_t* Ag = A + ((long)g * Nn + row0) * KW;
    uint32_t* Yb = Yout + ((long)g * Nn + row0) * (Hh / 2);

    // A chunk: 128 rows x 16 words = 512 x16B / 256 thr = 2 each
    // B chunk: 64 rows x 16 words = 256 x16B / 256 thr = 1 each
    #define ISSUE16(c, s) do { \
        _Pragma("unroll") \
        for (int i = 0; i < 2; i++) { \
            int f = t + i * 256; \
            int row = f >> 2, c4 = f & 3; \
            cp16(&AsBase[(s) * ABUFW + row * WPITCH + c4 * 4], \
                 &Ag[(long)row * KW + (c) * 16 + c4 * 4]); \
        } \
        { \
            int row = t >> 2, c4 = t & 3; \
            cp16(&BsBase[(s) * BBUFW + row * WPITCH + c4 * 4], \
                 &Bt[(long)(col0 + row) * KW + (c) * 16 + c4 * 4]); \
        } \
        CP_COMMIT(); \
    } while (0)

    float acc[2][4][4] = {};
    ISSUE16(0, 0);
    ISSUE16(1, 1);

    for (int c = 0; c < NC; c++) {
        if (c + 1 < NC) CP_WAIT1(); else CP_WAIT0();
        __syncthreads();
        if (c + 2 < NC) ISSUE16(c + 2, (c + 2) % NSTAGE);

        const uint32_t* As = AsBase + (c % NSTAGE) * ABUFW;
        const uint32_t* Bs = BsBase + (c % NSTAGE) * BBUFW;

        #pragma unroll
        for (int ks = 0; ks < 2; ks++) {        // two K16 steps per 32-bf16 chunk
            const int kw = ks * 8 + tig;
            uint32_t a[2][4];
            #pragma unroll
            for (int mt = 0; mt < 2; mt++) {
                int mr = wy * 32 + mt * 16 + gid;
                a[mt][0] = As[(mr    ) * WPITCH + kw];
                a[mt][1] = As[(mr + 8) * WPITCH + kw];
                a[mt][2] = As[(mr    ) * WPITCH + kw + 4];
                a[mt][3] = As[(mr + 8) * WPITCH + kw + 4];
            }
            uint32_t b[4][2];
            #pragma unroll
            for (int nt = 0; nt < 4; nt++) {
                int nr = wx * 32 + nt * 8 + gid;
                b[nt][0] = Bs[nr * WPITCH + kw];
                b[nt][1] = Bs[nr * WPITCH + kw + 4];
            }
            #pragma unroll
            for (int mt = 0; mt < 2; mt++)
                #pragma unroll
                for (int nt = 0; nt < 4; nt++)
                    mma_bf16(acc[mt][nt][0], acc[mt][nt][1],
                             acc[mt][nt][2], acc[mt][nt][3],
                             a[mt][0], a[mt][1], a[mt][2], a[mt][3],
                             b[nt][0], b[nt][1]);
        }
    }

    #pragma unroll
    for (int mt = 0; mt < 2; mt++) {
        int r = wy * 32 + mt * 16 + gid;
        #pragma unroll
        for (int nt = 0; nt < 4; nt++) {
            int cc = col0 + wx * 32 + nt * 8 + 2 * tig;
            __nv_bfloat162 p0 = __float22bfloat162_rn(
                make_float2(acc[mt][nt][0], acc[mt][nt][1]));
            __nv_bfloat162 p1 = __float22bfloat162_rn(
                make_float2(acc[mt][nt][2], acc[mt][nt][3]));
            Yb[(long)r * (Hh / 2) + cc / 2]       = *reinterpret_cast<uint32_t*>(&p0);
            Yb[(long)(r + 8) * (Hh / 2) + cc / 2] = *reinterpret_cast<uint32_t*>(&p1);
        }
    }
}

// ---------------- SpMM: X = act(A_sparse @ Yb + bias) ------------------------
// LAST=false: relu -> bf16 g_Xb.  LAST=true: softmax + fp32 X0 -> fp32 g_X.
template<bool LAST>
__global__ __launch_bounds__(128)
void spmm_kernel(const float* __restrict__ bias) {
    int g = blockIdx.y;
    int n = blockIdx.x;
    int t = threadIdx.x;
    int lane = t & 31, wid = t >> 5;
    long rbase = (long)g * Nn + n;
    int nnz = g_nnz[rbase];

    __shared__ unsigned short scol[CAP];
    __shared__ float sval[CAP];
    for (int j = t; j < nnz; j += 128) {
        scol[j] = g_cols[rbase * CAP + j];
        sval[j] = g_vals[rbase * CAP + j];
    }
    __syncthreads();

    const uint32_t* Yg = g_Yb + (long)g * Nn * (Hh / 2);
    float a0 = 0.f, a1 = 0.f;
    int j = 0;
    for (; j + 8 <= nnz; j += 8) {
        uint32_t w[8];
        #pragma unroll
        for (int q = 0; q < 8; q++)
            w[q] = Yg[(long)scol[j + q] * (Hh / 2) + t];
        #pragma unroll
        for (int q = 0; q < 8; q++) {
            float2 f = __bfloat1622float2(*reinterpret_cast<__nv_bfloat162*>(&w[q]));
            a0 += sval[j + q] * f.x;
            a1 += sval[j + q] * f.y;
        }
    }
    if (j + 4 <= nnz) {
        uint32_t w[4];
        #pragma unroll
        for (int q = 0; q < 4; q++)
            w[q] = Yg[(long)scol[j + q] * (Hh / 2) + t];
        #pragma unroll
        for (int q = 0; q < 4; q++) {
            float2 f = __bfloat1622float2(*reinterpret_cast<__nv_bfloat162*>(&w[q]));
            a0 += sval[j + q] * f.x;
            a1 += sval[j + q] * f.y;
        }
        j += 4;
    }
    for (; j < nnz; j++) {
        uint32_t w = Yg[(long)scol[j] * (Hh / 2) + t];
        float2 f = __bfloat1622float2(*reinterpret_cast<__nv_bfloat162*>(&w));
        a0 += sval[j] * f.x;
        a1 += sval[j] * f.y;
    }

    float2 bv = *reinterpret_cast<const float2*>(&bias[2 * t]);
    float v0 = a0 + bv.x, v1 = a1 + bv.y;

    if (!LAST) {
        __nv_bfloat162 p = __float22bfloat162_rn(
            make_float2(fmaxf(v0, 0.f), fmaxf(v1, 0.f)));
        g_Xb[rbase * (Hh / 2) + t] = *reinterpret_cast<uint32_t*>(&p);
    } else {
        __shared__ float smax[4], ssum[4];
        float m = fmaxf(v0, v1);
        #pragma unroll
        for (int off = 16; off > 0; off >>= 1)
            m = fmaxf(m, __shfl_xor_sync(0xFFFFFFFFu, m, off));
        if (lane == 0) smax[wid] = m;
        __syncthreads();
        m = fmaxf(fmaxf(smax[0], smax[1]), fmaxf(smax[2], smax[3]));
        float e0 = expf(v0 - m), e1 = expf(v1 - m);
        float s = e0 + e1;
        #pragma unroll
        for (int off = 16; off > 0; off >>= 1)
            s += __shfl_xor_sync(0xFFFFFFFFu, s, off);
        if (lane == 0) ssum[wid] = s;
        __syncthreads();
        s = (ssum[0] + ssum[1]) + (ssum[2] + ssum[3]);
        float inv = 1.0f / s;
        float2 x0 = reinterpret_cast<const float2*>(g_X0)[rbase * (Hh / 2) + t];
        reinterpret_cast<float2*>(g_X)[rbase * (Hh / 2) + t] =
            make_float2(e0 * inv + x0.x, e1 * inv + x0.y);
    }
}

// ---------------- per-sample masked mean -------------------------------------
__global__ void masked_mean_kernel(const int* __restrict__ graph,
                                   float* __restrict__ out) {
    int b = blockIdx.x;
    int chunk = blockIdx.y;
    int h = threadIdx.x;
    int g = graph[b];
    const float* xg = g_X + ((long)g * Nn + chunk * 128) * Hh;
    const float* mb = g_maskf + (long)b * Nn + chunk * 128;
    float acc = 0.f;
    #pragma unroll 4
    for (int n = 0; n < 128; n++) {
        float mv = mb[n];
        if (mv != 0.f) acc += xg[(long)n * Hh + h];
    }
    atomicAdd(&out[(long)b * Hh + h], acc / g_cnt[b]);
}

// ---------------- launch -----------------------------------------------------
extern "C" void kernel_launch(void* const* d_in, const int* in_sizes, int n_in,
                              void* d_out, int out_size) {
    const int*   graph = (const int*)  d_in[0];
    const void*  mask  =               d_in[1];
    const float* xs    = (const float*)d_in[2];
    const float* Adj   = (const float*)d_in[3];
    const float* W_in  = (const float*)d_in[4];
    const float* b_in  = (const float*)d_in[5];
    const float* Ws    = (const float*)d_in[6];
    const float* bs    = (const float*)d_in[7];
    float* out = (float*)d_out;

    float *pWtIn;
    uint32_t *pX0b, *pXb, *pYb, *pWtb;
    cudaGetSymbolAddress((void**)&pWtIn, g_WtIn);
    cudaGetSymbolAddress((void**)&pX0b,  g_X0b);
    cudaGetSymbolAddress((void**)&pXb,   g_Xb);
    cudaGetSymbolAddress((void**)&pYb,   g_Yb);
    cudaGetSymbolAddress((void**)&pWtb,  g_Wtb);

    cudaFuncSetAttribute(mma_gemm_in_kernel,
        cudaFuncAttributeMaxDynamicSharedMemorySize, (int)GEMM32_SMEM);
    cudaFuncSetAttribute(mma_gemm_bf16_kernel,
        cudaFuncAttributeMaxDynamicSharedMemorySize, (int)GEMM16_SMEM);

    // prep: zero d_out + detect mask dtype + weight transposes
    prep_kernel<<<Bb + 320, dim3(32, 8)>>>((const unsigned int*)mask, out, Ws, W_in);

    // CSR build + mask expand
    dim3 cm_grid(Nn, Gg + 1);
    csr_mask_kernel<<<cm_grid, 256>>>(Adj, mask);

    dim3 ggrid(Hh / 64, Nn / 128, Gg);   // 256 CTAs

    // X0 = relu(xs @ W_in + b_in)  [tf32; fp32 + bf16 copies]
    mma_gemm_in_kernel<<<ggrid, 256, GEMM32_SMEM>>>(xs, pWtIn, b_in);

    dim3 sp_grid(Nn, Gg);
    const uint32_t* xin = pX0b;
    for (int i = 0; i < Ll; i++) {
        mma_gemm_bf16_kernel<<<ggrid, 256, GEMM16_SMEM>>>(
            xin, pWtb + (long)i * Hh * Hh / 2, pYb);
        if (i < Ll - 1)
            spmm_kernel<false><<<sp_grid, 128>>>(bs + (long)i * Hh);
        else
            spmm_kernel<true><<<sp_grid, 128>>>(bs + (long)i * Hh);
        xin = pXb;
    }

    dim3 mm_grid(Bb, Nn / 128);
    masked_mean_kernel<<<mm_grid, Hh>>>(graph, out);
}